// round 5
// baseline (speedup 1.0000x reference)
#include <cuda_runtime.h>
#include <cuda_fp16.h>

#define BB  8
#define TT  1000
#define NHH 8
#define DD  64

// -(1/sqrt(64)) * log2(e), divided by int8 scale 256
#define QSCALE      256.0f
#define SCALE_COMB  (-0.18033688011112042f / 256.0f)

// Scratch (no allocs allowed)
__device__ unsigned g_qpack[BB*NHH*TT*16];  // int8x4 packed q, [b,h,t,dg]
__device__ unsigned g_kpack[BB*NHH*TT*16];  // int8x4 packed k
__device__ unsigned g_vpack[BB*NHH*TT*32];  // half2 packed v, [b,h,t,wp]
__device__ float    g_ho   [BB*NHH*TT*DD];  // per-head attention outputs

__device__ __forceinline__ int sad4_(int acc, unsigned a, unsigned b) {
  int r;
  asm("vabsdiff4.s32.s32.s32.add %0, %1, %2, %3;"
      : "=r"(r) : "r"(a), "r"(b), "r"(acc));
  return r;
}

__device__ __forceinline__ int q8_(float v) {
  int q = __float2int_rn(v * QSCALE);
  return max(-127, min(127, q));
}
__device__ __forceinline__ unsigned pack4_(int a, int b, int c, int d) {
  return (unsigned)(a & 255) | ((unsigned)(b & 255) << 8) |
         ((unsigned)(c & 255) << 16) | ((unsigned)(d & 255) << 24);
}

// ---------------------------------------------------------------------------
// K0: pack k = x * wk[h] -> int8x4. One thread per (h, token) pair.
// ---------------------------------------------------------------------------
__global__ __launch_bounds__(256) void kpack_kernel(
    const float* __restrict__ x, const float* __restrict__ wk) {
  __shared__ float xs[32][68];
  __shared__ float wks[512];
  const int tid = threadIdx.x;
  const int tok0 = blockIdx.x * 32;

  for (int i = tid; i < 512; i += 256) wks[i] = wk[i];
  for (int i = tid; i < 32*16; i += 256) {
    int tl = i >> 4, k4 = (i & 15) << 2;
    float4 v = *(const float4*)&x[(tok0 + tl)*DD + k4];
    xs[tl][k4+0] = v.x; xs[tl][k4+1] = v.y;
    xs[tl][k4+2] = v.z; xs[tl][k4+3] = v.w;
  }
  __syncthreads();

  const int h = tid >> 5, tl = tid & 31;
  const int gt = tok0 + tl;
  const int b = gt / TT, t = gt - b*TT;
  unsigned orow[16];
  #pragma unroll
  for (int dg = 0; dg < 16; dg++) {
    int d = dg << 2;
    orow[dg] = pack4_(q8_(xs[tl][d+0] * wks[h*64 + d+0]),
                      q8_(xs[tl][d+1] * wks[h*64 + d+1]),
                      q8_(xs[tl][d+2] * wks[h*64 + d+2]),
                      q8_(xs[tl][d+3] * wks[h*64 + d+3]));
  }
  unsigned* dst = g_kpack + ((size_t)(b*NHH + h)*TT + t)*16;
  #pragma unroll
  for (int i = 0; i < 4; i++)
    *(uint4*)&dst[i*4] = make_uint4(orow[i*4], orow[i*4+1], orow[i*4+2], orow[i*4+3]);
}

// ---------------------------------------------------------------------------
// K1: fused Q/V projection GEMM. z=0: q -> int8x4 pack; z=1: v -> half2 pack.
// ---------------------------------------------------------------------------
__global__ __launch_bounds__(256) void qv_kernel(
    const float* __restrict__ x, const float* __restrict__ wq,
    const float* __restrict__ wv) {
  const float* w = blockIdx.z ? wv : wq;
  const int m0 = blockIdx.x * 64;
  const int n0 = blockIdx.y * 64;

  __shared__ float xs[64*68];
  __shared__ float ws[64*68];
  const int tid = threadIdx.x;

  for (int i = tid; i < 64*16; i += 256) {
    int m = i >> 4, k4 = (i & 15) << 2;
    float4 v4 = *(const float4*)&x[(m0 + m)*DD + k4];
    xs[(k4+0)*68 + m] = v4.x;
    xs[(k4+1)*68 + m] = v4.y;
    xs[(k4+2)*68 + m] = v4.z;
    xs[(k4+3)*68 + m] = v4.w;
  }
  for (int i = tid; i < 64*64; i += 256) {
    int n = i >> 6, k = i & 63;
    ws[k*68 + n] = w[(n0 + n)*65 + k];
  }
  __syncthreads();

  const int tm = (tid >> 4) * 4;
  const int tn = (tid & 15) * 4;
  float acc[4][4];
  #pragma unroll
  for (int i = 0; i < 4; i++)
    #pragma unroll
    for (int j = 0; j < 4; j++) acc[i][j] = 0.f;

  #pragma unroll 8
  for (int k = 0; k < 64; k++) {
    float4 a4 = *(const float4*)&xs[k*68 + tm];
    float4 b4 = *(const float4*)&ws[k*68 + tn];
    float av[4] = {a4.x, a4.y, a4.z, a4.w};
    float bv[4] = {b4.x, b4.y, b4.z, b4.w};
    #pragma unroll
    for (int i = 0; i < 4; i++)
      #pragma unroll
      for (int j = 0; j < 4; j++) acc[i][j] += av[i] * bv[j];
  }

  const int n = n0 + tn;
  const int h = n >> 6, d0 = n & 63;
  float b0 = w[(n+0)*65 + 64];
  float b1 = w[(n+1)*65 + 64];
  float b2 = w[(n+2)*65 + 64];
  float b3 = w[(n+3)*65 + 64];

  #pragma unroll
  for (int i = 0; i < 4; i++) {
    int m = m0 + tm + i;
    int b = m / TT, t = m - b*TT;
    float f0 = acc[i][0] + b0, f1 = acc[i][1] + b1;
    float f2 = acc[i][2] + b2, f3 = acc[i][3] + b3;
    size_t row = (size_t)(b*NHH + h)*TT + t;
    if (blockIdx.z == 0) {
      g_qpack[row*16 + (d0 >> 2)] = pack4_(q8_(f0), q8_(f1), q8_(f2), q8_(f3));
    } else {
      __half2 h01 = __floats2half2_rn(f0, f1);
      __half2 h23 = __floats2half2_rn(f2, f3);
      uint2 o;
      o.x = *(unsigned*)&h01;
      o.y = *(unsigned*)&h23;
      *(uint2*)&g_vpack[row*32 + (d0 >> 1)] = o;
    }
  }
}

// ---------------------------------------------------------------------------
// K2: L1-distance attention.
//   scores: int8 SAD (vabsdiff4.add) on the ALU pipe, 4 dims/instr
//   AV:     HFMA2, 32-s chunks drained to fp32
// softmax max == 0 exactly (scores <= 0, null logit = 0): p=exp(s),
// denom = 1 + sum p (shared atomics).
// ---------------------------------------------------------------------------
__global__ __launch_bounds__(128, 4) void attn_kernel() {
  __shared__ unsigned qpk[16*68];   // [dg][t]  int8x4, stride 68
  __shared__ unsigned kpk[16*68];   // [dg][s]  int8x4, stride 68
  __shared__ unsigned vsh[64*32];   // [s][wp]  half2 bits
  __shared__ unsigned ps2[64*68];   // [s][t]   half2 duplicated, stride 68
  __shared__ float    denom[64];

  const int b  = blockIdx.z;
  const int h  = blockIdx.y;
  const int t0 = blockIdx.x * 64;
  const int tid = threadIdx.x;
  const int tt  = (tid & 15) * 4;  // 4 query rows
  const int g8  = (tid >> 4) * 8;  // 8 sources (score) / 8 dims (AV)
  const int sp0 = g8 >> 1;         // 4 half2 dim-pairs

  if (tid < 64) denom[tid] = 0.f;

  const unsigned* qpg = g_qpack + (size_t)(b*NHH + h)*TT*16;
  const unsigned* kpg = g_kpack + (size_t)(b*NHH + h)*TT*16;
  const unsigned* vpg = g_vpack + (size_t)(b*NHH + h)*TT*32;

  // load q tile transposed [dg][t]
  for (int i = tid; i < 256; i += 128) {
    int t = i >> 2, dg4 = (i & 3) << 2;
    int trow = t0 + t; if (trow >= TT) trow = TT - 1;  // clamp; masked later
    uint4 v = *(const uint4*)&qpg[(size_t)trow*16 + dg4];
    qpk[(dg4+0)*68 + t] = v.x;
    qpk[(dg4+1)*68 + t] = v.y;
    qpk[(dg4+2)*68 + t] = v.z;
    qpk[(dg4+3)*68 + t] = v.w;
  }
  __syncthreads();

  float oacc[4][8];
  #pragma unroll
  for (int i = 0; i < 4; i++)
    #pragma unroll
    for (int j = 0; j < 8; j++) oacc[i][j] = 0.f;

  for (int s0 = 0; s0 < TT; s0 += 64) {
    // load k transposed [dg][s], v direct [s][wp]
    for (int i = tid; i < 256; i += 128) {
      int s = i >> 2, dg4 = (i & 3) << 2;
      int srow = s0 + s; if (srow >= TT) srow = TT - 1;  // clamp; e masked to 0
      uint4 v = *(const uint4*)&kpg[(size_t)srow*16 + dg4];
      kpk[(dg4+0)*68 + s] = v.x;
      kpk[(dg4+1)*68 + s] = v.y;
      kpk[(dg4+2)*68 + s] = v.z;
      kpk[(dg4+3)*68 + s] = v.w;
    }
    for (int i = tid; i < 512; i += 128) {
      int s = i >> 3, w8 = (i & 7) << 2;
      int srow = s0 + s; if (srow >= TT) srow = TT - 1;  // p=0 kills it
      *(uint4*)&vsh[s*32 + w8] = *(const uint4*)&vpg[(size_t)srow*32 + w8];
    }
    __syncthreads();

    // ---- scores via SAD ----
    int sacc[4][8];
    #pragma unroll
    for (int i = 0; i < 4; i++)
      #pragma unroll
      for (int j = 0; j < 8; j++) sacc[i][j] = 0;

    #pragma unroll 8
    for (int dg = 0; dg < 16; dg++) {
      uint4 q4 = *(const uint4*)&qpk[dg*68 + tt];
      uint4 ka = *(const uint4*)&kpk[dg*68 + g8];
      uint4 kb = *(const uint4*)&kpk[dg*68 + g8 + 4];
      unsigned qa[4] = {q4.x, q4.y, q4.z, q4.w};
      unsigned kk[8] = {ka.x, ka.y, ka.z, ka.w, kb.x, kb.y, kb.z, kb.w};
      #pragma unroll
      for (int i = 0; i < 4; i++)
        #pragma unroll
        for (int j = 0; j < 8; j++)
          sacc[i][j] = sad4_(sacc[i][j], qa[i], kk[j]);
    }

    // e = exp2(SCALE_COMB * sad), masked past T
    float ef[4][8];
    #pragma unroll
    for (int i = 0; i < 4; i++)
      #pragma unroll
      for (int j = 0; j < 8; j++) {
        float f = (float)sacc[i][j] * SCALE_COMB;
        float e;
        asm("ex2.approx.f32 %0, %1;" : "=f"(e) : "f"(f));
        if (s0 + g8 + j >= TT) e = 0.f;
        ef[i][j] = e;
      }

    // denom partials: one shared atomic per query
    #pragma unroll
    for (int i = 0; i < 4; i++) {
      float ds = ((ef[i][0] + ef[i][1]) + (ef[i][2] + ef[i][3]))
               + ((ef[i][4] + ef[i][5]) + (ef[i][6] + ef[i][7]));
      atomicAdd(&denom[tt + i], ds);
    }

    // store p duplicated as half2, transposed [s][t]
    #pragma unroll
    for (int j = 0; j < 8; j++) {
      __half2 pv[4];
      pv[0] = __floats2half2_rn(ef[0][j], ef[0][j]);
      pv[1] = __floats2half2_rn(ef[1][j], ef[1][j]);
      pv[2] = __floats2half2_rn(ef[2][j], ef[2][j]);
      pv[3] = __floats2half2_rn(ef[3][j], ef[3][j]);
      *(uint4*)&ps2[(g8+j)*68 + tt] = *(uint4*)pv;
    }
    __syncthreads();

    // ---- AV: HFMA2, 32-s chunks drained to fp32 ----
    const __half2* pp2 = (const __half2*)ps2 + tt;
    const __half2* vp2 = (const __half2*)vsh + sp0;
    #pragma unroll
    for (int half_ = 0; half_ < 2; half_++) {
      __half2 oa2[4][4];
      #pragma unroll
      for (int i = 0; i < 4; i++)
        #pragma unroll
        for (int jp = 0; jp < 4; jp++) oa2[i][jp] = __float2half2_rn(0.f);

      #pragma unroll 4
      for (int ss = 0; ss < 32; ss++) {
        int s = half_*32 + ss;
        __half2 pb[4];
        *(uint4*)pb = *(const uint4*)(pp2 + s*68);
        __half2 vv[4];
        *(uint4*)vv = *(const uint4*)(vp2 + s*32);
        #pragma unroll
        for (int i = 0; i < 4; i++)
          #pragma unroll
          for (int jp = 0; jp < 4; jp++)
            oa2[i][jp] = __hfma2(pb[i], vv[jp], oa2[i][jp]);
      }
      #pragma unroll
      for (int i = 0; i < 4; i++)
        #pragma unroll
        for (int jp = 0; jp < 4; jp++) {
          float2 f = __half22float2(oa2[i][jp]);
          oacc[i][2*jp+0] += f.x;
          oacc[i][2*jp+1] += f.y;
        }
    }
    __syncthreads();
  }

  // normalize by (1 + sum p) and store per-head output
  float* hop = g_ho + (size_t)(b*NHH + h)*TT*DD;
  #pragma unroll
  for (int i = 0; i < 4; i++) {
    int trow = t0 + tt + i;
    if (trow < TT) {
      float inv = 1.f / (1.f + denom[tt + i]);
      float4 o1, o2;
      o1.x = oacc[i][0]*inv; o1.y = oacc[i][1]*inv;
      o1.z = oacc[i][2]*inv; o1.w = oacc[i][3]*inv;
      o2.x = oacc[i][4]*inv; o2.y = oacc[i][5]*inv;
      o2.z = oacc[i][6]*inv; o2.w = oacc[i][7]*inv;
      *(float4*)&hop[trow*DD + g8]     = o1;
      *(float4*)&hop[trow*DD + g8 + 4] = o2;
    }
  }
}

// ---------------------------------------------------------------------------
// K3: sum over heads, ReLU, y = Wf . r + bias, out = x + y.
// ---------------------------------------------------------------------------
__global__ __launch_bounds__(256) void out_kernel(
    const float* __restrict__ x, const float* __restrict__ wf,
    float* __restrict__ out) {
  __shared__ float r[4][64];
  __shared__ float wfs[64*65];
  const int tl = threadIdx.x >> 6;
  const int w  = threadIdx.x & 63;
  const int token = blockIdx.x*4 + tl;
  const int b = token / TT, t = token - b*TT;

  for (int i = threadIdx.x; i < 64*65; i += 256) wfs[i] = wf[i];

  float s = 0.f;
  #pragma unroll
  for (int h = 0; h < NHH; h++)
    s += g_ho[((size_t)(b*NHH + h)*TT + t)*DD + w];
  r[tl][w] = fmaxf(s, 0.f);
  __syncthreads();

  float acc = wfs[w*65 + 64];
  #pragma unroll 8
  for (int k = 0; k < 64; k++)
    acc += wfs[w*65 + k] * r[tl][k];

  out[(size_t)token*DD + w] = x[(size_t)token*DD + w] + acc;
}

// ---------------------------------------------------------------------------
extern "C" void kernel_launch(void* const* d_in, const int* in_sizes, int n_in,
                              void* d_out, int out_size) {
  const float* x  = (const float*)d_in[0];  // [8,1000,64]
  const float* wq = (const float*)d_in[1];  // [512,65]
  const float* wv = (const float*)d_in[2];  // [512,65]
  const float* wk = (const float*)d_in[3];  // [8,64]
  const float* wf = (const float*)d_in[4];  // [64,65]
  float* out = (float*)d_out;               // [8,1000,64]

  (void)in_sizes; (void)n_in; (void)out_size;

  kpack_kernel<<<BB*TT/32, 256>>>(x, wk);
  qv_kernel<<<dim3(8000/64, 512/64, 2), 256>>>(x, wq, wv);
  attn_kernel<<<dim3(16, NHH, BB), 128>>>();
  out_kernel<<<8000/4, 256>>>(x, wf, out);
}